// round 16
// baseline (speedup 1.0000x reference)
#include <cuda_runtime.h>
#include <cuda_bf16.h>
#include <cstdint>

#define D 128
#define NMAX 100000
#define EMAX 1600000
#define NBLK 98                         // ceil(NMAX/1024)
#define WTILE (128 * 128)
#define PITCH 272                       // smem row pitch in bytes (136 bf16)
#define BM 64                           // GEMM row-tile (2 CTAs/SM)
#define ATILE64 (BM * PITCH)            // 17408 B (A hi or lo tile)
#define BTILE (128 * PITCH)             // 34816 B (B hi or lo tile)
#define DYNSMEM (2 * ATILE64 + 2 * BTILE)   // 104448 B
#define BN_EPS 1e-5f
#define AGG_W 10                        // aggregation batch width

// ---- scratch (static device globals; no allocation allowed) ----
__device__ float  g_h[(size_t)NMAX * D];     // GEMM out / edge gather src
__device__ float  g_acc[(size_t)NMAX * D];   // aggregation output
__device__ float  g_dinv[NMAX];              // deg^-0.5
__device__ double g_stats4[4][2 * D];        // per-layer BN sum/sumsq
__device__ __align__(16) __nv_bfloat16 g_wbh[4 * WTILE];  // W^T hi (bf16)
__device__ __align__(16) __nv_bfloat16 g_wbl[4 * WTILE];  // W^T lo residual
// CSR-by-destination structures
__device__ int    g_colcnt[NMAX];
__device__ int    g_colptr[NMAX + 1];
__device__ int    g_cursor[NMAX];
__device__ int    g_blksum[NBLK + 1];
__device__ int    g_blkoff[NBLK + 1];
__device__ __align__(16) int4 g_epack[EMAX]; // {row, bits(a0), bits(a1), bits(a2)}
__device__ float  g_enrm[EMAX];              // dinv[row]*dinv[col], edge order

__device__ __forceinline__ uint32_t pack_bf2(__nv_bfloat16 lo, __nv_bfloat16 hi) {
    return ((uint32_t)__bfloat16_as_ushort(hi) << 16) |
           (uint32_t)__bfloat16_as_ushort(lo);
}

// ------------------------------------------------------------------
// Degree (by row, float -> dinv) + in-degree histogram (by col, int)
// ------------------------------------------------------------------
__global__ void k_count(const int* __restrict__ ei, int E) {
    for (int i = blockIdx.x * blockDim.x + threadIdx.x; i < E;
         i += gridDim.x * blockDim.x) {
        atomicAdd(&g_dinv[ei[i]], 1.0f);
        atomicAdd(&g_colcnt[ei[E + i]], 1);
    }
}

__global__ void k_dinv(int M) {
    int i = blockIdx.x * blockDim.x + threadIdx.x;
    if (i < M) g_dinv[i] = rsqrtf(g_dinv[i] + 1.0f);
}

// ---- 3-phase exclusive scan of colcnt -> colptr ----
__global__ void k_scan1(int M) {        // grid=NBLK, block=1024
    __shared__ int sm[1024];
    int tid = threadIdx.x;
    int i   = blockIdx.x * 1024 + tid;
    int v   = (i < M) ? g_colcnt[i] : 0;
    sm[tid] = v;
    __syncthreads();
    #pragma unroll
    for (int off = 1; off < 1024; off <<= 1) {
        int t = (tid >= off) ? sm[tid - off] : 0;
        __syncthreads();
        sm[tid] += t;
        __syncthreads();
    }
    if (i < M) g_colptr[i] = sm[tid] - v;   // block-local exclusive
    if (tid == 1023) g_blksum[blockIdx.x] = sm[1023];
}

__global__ void k_scan2(int nb) {       // 1 block x 128 threads
    __shared__ int sm[128];
    int tid = threadIdx.x;
    int v = (tid < nb) ? g_blksum[tid] : 0;
    sm[tid] = v;
    __syncthreads();
    #pragma unroll
    for (int off = 1; off < 128; off <<= 1) {
        int t = (tid >= off) ? sm[tid - off] : 0;
        __syncthreads();
        sm[tid] += t;
        __syncthreads();
    }
    if (tid <= nb) g_blkoff[tid] = sm[tid] - v;   // exclusive
}

__global__ void k_scan3(int M, int E) {
    int i = blockIdx.x * blockDim.x + threadIdx.x;
    if (i < M) {
        int p = g_colptr[i] + g_blkoff[i >> 10];
        g_colptr[i] = p;
        g_cursor[i] = p;
    }
    if (i == 0) g_colptr[M] = E;
}

// ---- fill packed CSR records + precomputed per-edge norm ----
__global__ void k_fill(const int* __restrict__ ei,
                       const float* __restrict__ ea, int E) {
    for (int i = blockIdx.x * blockDim.x + threadIdx.x; i < E;
         i += gridDim.x * blockDim.x) {
        int r = ei[i], c = ei[E + i];
        int pos = atomicAdd(&g_cursor[c], 1);
        int4 p;
        p.x = r;
        p.y = __float_as_int(ea[3 * i + 0]);
        p.z = __float_as_int(ea[3 * i + 1]);
        p.w = __float_as_int(ea[3 * i + 2]);
        g_epack[pos] = p;
        g_enrm[pos]  = g_dinv[r] * g_dinv[c];
    }
}

// ------------------------------------------------------------------
// Weight conversion: Wt[n][k] = split_bf16(W[k][n]) for 4 matrices
// ------------------------------------------------------------------
__global__ void k_wconv(const float* __restrict__ W0, const float* __restrict__ W1,
                        const float* __restrict__ W2, const float* __restrict__ W3) {
    int i = blockIdx.x * blockDim.x + threadIdx.x;
    if (i >= 4 * WTILE) return;
    int m = i >> 14, r = i & (WTILE - 1);
    int n = r >> 7, k = r & 127;
    const float* W = (m == 0) ? W0 : (m == 1) ? W1 : (m == 2) ? W2 : W3;
    float v = W[k * 128 + n];
    __nv_bfloat16 h = __float2bfloat16_rn(v);
    g_wbh[i] = h;
    g_wbl[i] = __float2bfloat16_rn(v - __bfloat162float(h));
}

// ------------------------------------------------------------------
// Tensor-core split-bf16 GEMM, BM=64 tile (2 CTAs/SM):
//   C[M,128] = act(A)[M,128] @ W[128,128] + bias
//   act(A) = stats ? relu(A)*mul+add : A  (BN coeffs from stats in-CTA)
//   C = (Ah + Al)@Bh + Ah@Bl
// Warp w: rows (w&3)*16.., cols (w>>2)*64.. (8 n-tiles each)
// ------------------------------------------------------------------
__global__ __launch_bounds__(256, 2)
void k_gemm_mma(const float* __restrict__ A,
                const __nv_bfloat16* __restrict__ Bh,
                const __nv_bfloat16* __restrict__ Bl,
                const float* __restrict__ bias,
                const float* __restrict__ gam,   // nullable -> no BN
                const float* __restrict__ bet,
                const double* __restrict__ stats,
                float* __restrict__ C, int M)
{
    extern __shared__ char dsm[];
    char* pAh = dsm;
    char* pAl = dsm + ATILE64;
    char* pBh = dsm + 2 * ATILE64;
    char* pBl = dsm + 2 * ATILE64 + BTILE;
    __shared__ float s_bias[128], s_mul[128], s_add[128];

    const int tid  = threadIdx.x;
    const int warp = tid >> 5;
    const int lane = tid & 31;
    const int g    = lane >> 2;
    const int tig  = lane & 3;
    const int m0   = blockIdx.x * BM;
    const bool useBN = (gam != nullptr);

    if (tid < 128) {
        s_bias[tid] = bias[tid];
        if (useBN) {
            double mean = stats[tid] / (double)M;
            double var  = stats[D + tid] / (double)M - mean * mean;
            float mul = gam[tid] * rsqrtf((float)var + BN_EPS);
            s_mul[tid] = mul;
            s_add[tid] = bet[tid] - (float)mean * mul;
        }
    }
    __syncthreads();   // s_mul/s_add read by all threads below

    // B tiles: 128 rows x 128 bf16
    #pragma unroll
    for (int it = 0; it < 8; it++) {
        int q = it * 256 + tid;
        int row = q >> 4, c8 = (q & 15) << 3;
        *(uint4*)(pBh + row * PITCH + c8 * 2) = *(const uint4*)(Bh + row * 128 + c8);
        *(uint4*)(pBl + row * PITCH + c8 * 2) = *(const uint4*)(Bl + row * 128 + c8);
    }

    // A tile: 64 rows, fused relu+BN, split to bf16 hi/lo
    #pragma unroll
    for (int it = 0; it < 8; it++) {
        int q = it * 256 + tid;
        int row = q >> 5, c4 = (q & 31) << 2;
        int grow = m0 + row;
        float4 v = make_float4(0.f, 0.f, 0.f, 0.f);
        if (grow < M) v = *(const float4*)(A + (size_t)grow * 128 + c4);
        float vv[4] = {v.x, v.y, v.z, v.w};
        if (useBN) {
            #pragma unroll
            for (int j = 0; j < 4; j++)
                vv[j] = fmaxf(vv[j], 0.f) * s_mul[c4 + j] + s_add[c4 + j];
        }
        __nv_bfloat16 h[4], l[4];
        #pragma unroll
        for (int j = 0; j < 4; j++) {
            h[j] = __float2bfloat16_rn(vv[j]);
            l[j] = __float2bfloat16_rn(vv[j] - __bfloat162float(h[j]));
        }
        uint2 hw, lw;
        hw.x = pack_bf2(h[0], h[1]); hw.y = pack_bf2(h[2], h[3]);
        lw.x = pack_bf2(l[0], l[1]); lw.y = pack_bf2(l[2], l[3]);
        *(uint2*)(pAh + row * PITCH + c4 * 2) = hw;
        *(uint2*)(pAl + row * PITCH + c4 * 2) = lw;
    }
    __syncthreads();

    float acc[8][4];
    #pragma unroll
    for (int nt = 0; nt < 8; nt++)
        #pragma unroll
        for (int j = 0; j < 4; j++) acc[nt][j] = 0.0f;

    const int arow  = (warp & 3) * 16;
    const int nbase = (warp >> 2) * 64;

    // ---- pass 1: (Ah + Al) @ Bh ----
    #pragma unroll
    for (int k8 = 0; k8 < 8; k8++) {
        uint32_t abase = (uint32_t)(arow + g) * PITCH + (uint32_t)k8 * 32 + 4u * tig;
        uint32_t ah[4], al[4];
        ah[0] = *(const uint32_t*)(pAh + abase);
        ah[1] = *(const uint32_t*)(pAh + abase + 8 * PITCH);
        ah[2] = *(const uint32_t*)(pAh + abase + 16);
        ah[3] = *(const uint32_t*)(pAh + abase + 8 * PITCH + 16);
        al[0] = *(const uint32_t*)(pAl + abase);
        al[1] = *(const uint32_t*)(pAl + abase + 8 * PITCH);
        al[2] = *(const uint32_t*)(pAl + abase + 16);
        al[3] = *(const uint32_t*)(pAl + abase + 8 * PITCH + 16);
        #pragma unroll
        for (int nt = 0; nt < 8; nt++) {
            uint32_t boff = (uint32_t)(nbase + nt * 8 + g) * PITCH + 4u * tig + k8 * 32;
            uint32_t b0 = *(const uint32_t*)(pBh + boff);
            uint32_t b1 = *(const uint32_t*)(pBh + boff + 16);
            asm volatile(
                "mma.sync.aligned.m16n8k16.row.col.f32.bf16.bf16.f32 "
                "{%0,%1,%2,%3}, {%4,%5,%6,%7}, {%8,%9}, {%0,%1,%2,%3};"
                : "+f"(acc[nt][0]), "+f"(acc[nt][1]),
                  "+f"(acc[nt][2]), "+f"(acc[nt][3])
                : "r"(ah[0]), "r"(ah[1]), "r"(ah[2]), "r"(ah[3]),
                  "r"(b0), "r"(b1));
            asm volatile(
                "mma.sync.aligned.m16n8k16.row.col.f32.bf16.bf16.f32 "
                "{%0,%1,%2,%3}, {%4,%5,%6,%7}, {%8,%9}, {%0,%1,%2,%3};"
                : "+f"(acc[nt][0]), "+f"(acc[nt][1]),
                  "+f"(acc[nt][2]), "+f"(acc[nt][3])
                : "r"(al[0]), "r"(al[1]), "r"(al[2]), "r"(al[3]),
                  "r"(b0), "r"(b1));
        }
    }
    // ---- pass 2: Ah @ Bl ----
    #pragma unroll
    for (int k8 = 0; k8 < 8; k8++) {
        uint32_t abase = (uint32_t)(arow + g) * PITCH + (uint32_t)k8 * 32 + 4u * tig;
        uint32_t ah[4];
        ah[0] = *(const uint32_t*)(pAh + abase);
        ah[1] = *(const uint32_t*)(pAh + abase + 8 * PITCH);
        ah[2] = *(const uint32_t*)(pAh + abase + 16);
        ah[3] = *(const uint32_t*)(pAh + abase + 8 * PITCH + 16);
        #pragma unroll
        for (int nt = 0; nt < 8; nt++) {
            uint32_t boff = (uint32_t)(nbase + nt * 8 + g) * PITCH + 4u * tig + k8 * 32;
            uint32_t b0 = *(const uint32_t*)(pBl + boff);
            uint32_t b1 = *(const uint32_t*)(pBl + boff + 16);
            asm volatile(
                "mma.sync.aligned.m16n8k16.row.col.f32.bf16.bf16.f32 "
                "{%0,%1,%2,%3}, {%4,%5,%6,%7}, {%8,%9}, {%0,%1,%2,%3};"
                : "+f"(acc[nt][0]), "+f"(acc[nt][1]),
                  "+f"(acc[nt][2]), "+f"(acc[nt][3])
                : "r"(ah[0]), "r"(ah[1]), "r"(ah[2]), "r"(ah[3]),
                  "r"(b0), "r"(b1));
        }
    }

    const int r0 = m0 + arow + g;
    const int r1 = r0 + 8;
    #pragma unroll
    for (int nt = 0; nt < 8; nt++) {
        int col = nbase + nt * 8 + tig * 2;
        float bx = s_bias[col], by = s_bias[col + 1];
        if (r0 < M) {
            float2 o = make_float2(acc[nt][0] + bx, acc[nt][1] + by);
            *(float2*)(C + (size_t)r0 * 128 + col) = o;
        }
        if (r1 < M) {
            float2 o = make_float2(acc[nt][2] + bx, acc[nt][3] + by);
            *(float2*)(C + (size_t)r1 * 128 + col) = o;
        }
    }
}

// ------------------------------------------------------------------
// CSR aggregation + fused BN statistics.
// ONE warp per destination node, lane owns 4 features.  Branch-free
// masked AGG_W-wide batches (30 independent loads per batch).
// __launch_bounds__(256,2) pins regs <=128 so 2 CTAs stay resident:
// 16 warps/SM x AGG_W=10 in-flight gathers = 160/SM (was 128).
// ------------------------------------------------------------------
__global__ __launch_bounds__(256, 2)
void k_aggr(const float* __restrict__ h, const float* __restrict__ We,
            const float* __restrict__ be, double* __restrict__ stats, int M)
{
    __shared__ double sm_s[128], sm_s2[128];
    const int tid  = threadIdx.x;
    const int lane = tid & 31;
    const int warp = (blockIdx.x * blockDim.x + tid) >> 5;
    const int nw   = (gridDim.x * blockDim.x) >> 5;
    const int f    = lane << 2;

    if (tid < 128) { sm_s[tid] = 0.0; sm_s2[tid] = 0.0; }
    __syncthreads();

    const float4 w0 = *(const float4*)(We + f);
    const float4 w1 = *(const float4*)(We + D + f);
    const float4 w2 = *(const float4*)(We + 2 * D + f);
    const float4 b4 = *(const float4*)(be + f);

    float ps[4]  = {0.f, 0.f, 0.f, 0.f};
    float ps2[4] = {0.f, 0.f, 0.f, 0.f};

    for (int n = warp; n < M; n += nw) {
        const int beg = g_colptr[n];
        const int end = g_colptr[n + 1];
        float4 acc = make_float4(0.f, 0.f, 0.f, 0.f);

        for (int pos = beg; pos < end; pos += AGG_W) {
            int idx[AGG_W];
            #pragma unroll
            for (int u = 0; u < AGG_W; u++) {
                int q = pos + u;
                idx[u] = (q < end) ? q : (end - 1);
            }
            int4   ee[AGG_W];
            float  nr[AGG_W];
            float4 hh[AGG_W];
            #pragma unroll
            for (int u = 0; u < AGG_W; u++) ee[u] = g_epack[idx[u]];
            #pragma unroll
            for (int u = 0; u < AGG_W; u++)
                nr[u] = (pos + u < end) ? g_enrm[idx[u]] : 0.0f;
            #pragma unroll
            for (int u = 0; u < AGG_W; u++)
                hh[u] = *(const float4*)(h + (size_t)ee[u].x * D + f);
            #pragma unroll
            for (int u = 0; u < AGG_W; u++) {
                float a0 = __int_as_float(ee[u].y);
                float a1 = __int_as_float(ee[u].z);
                float a2 = __int_as_float(ee[u].w);
                acc.x += fmaxf(hh[u].x + b4.x + a0*w0.x + a1*w1.x + a2*w2.x, 0.f) * nr[u];
                acc.y += fmaxf(hh[u].y + b4.y + a0*w0.y + a1*w1.y + a2*w2.y, 0.f) * nr[u];
                acc.z += fmaxf(hh[u].z + b4.z + a0*w0.z + a1*w1.z + a2*w2.z, 0.f) * nr[u];
                acc.w += fmaxf(hh[u].w + b4.w + a0*w0.w + a1*w1.w + a2*w2.w, 0.f) * nr[u];
            }
        }
        *(float4*)(g_acc + (size_t)n * D + f) = acc;

        // fused BN stats over relu(acc)
        float r0 = fmaxf(acc.x, 0.f), r1 = fmaxf(acc.y, 0.f);
        float r2 = fmaxf(acc.z, 0.f), r3 = fmaxf(acc.w, 0.f);
        ps[0] += r0; ps2[0] += r0 * r0;
        ps[1] += r1; ps2[1] += r1 * r1;
        ps[2] += r2; ps2[2] += r2 * r2;
        ps[3] += r3; ps2[3] += r3 * r3;
    }

    #pragma unroll
    for (int j = 0; j < 4; j++) {
        atomicAdd(&sm_s[f + j],  (double)ps[j]);
        atomicAdd(&sm_s2[f + j], (double)ps2[j]);
    }
    __syncthreads();
    if (tid < 128) {
        atomicAdd(&stats[tid],     sm_s[tid]);
        atomicAdd(&stats[D + tid], sm_s2[tid]);
    }
}

// ------------------------------------------------------------------
extern "C" void kernel_launch(void* const* d_in, const int* in_sizes, int n_in,
                              void* d_out, int out_size)
{
    const float* x  = (const float*)d_in[0];
    const int*   ei = (const int*)d_in[1];
    const float* ea = (const float*)d_in[2];
    const float* Wp[3]  = {(const float*)d_in[3],  (const float*)d_in[9],  (const float*)d_in[15]};
    const float* bp[3]  = {(const float*)d_in[4],  (const float*)d_in[10], (const float*)d_in[16]};
    const float* Wep[3] = {(const float*)d_in[5],  (const float*)d_in[11], (const float*)d_in[17]};
    const float* bep[3] = {(const float*)d_in[6],  (const float*)d_in[12], (const float*)d_in[18]};
    const float* gp[3]  = {(const float*)d_in[7],  (const float*)d_in[13], (const float*)d_in[19]};
    const float* btp[3] = {(const float*)d_in[8],  (const float*)d_in[14], (const float*)d_in[20]};
    const float* Wl = (const float*)d_in[21];
    const float* bl = (const float*)d_in[22];

    const int M = in_sizes[0] / D;
    const int E = in_sizes[1] / 2;

    // Resolve __device__ symbols via the runtime (GB300 ATS pitfall).
    void *p_h, *p_acc, *p_dinv, *p_stats, *p_wbh, *p_wbl, *p_colcnt;
    cudaGetSymbolAddress(&p_h, g_h);
    cudaGetSymbolAddress(&p_acc, g_acc);
    cudaGetSymbolAddress(&p_dinv, g_dinv);
    cudaGetSymbolAddress(&p_stats, g_stats4);
    cudaGetSymbolAddress(&p_wbh, g_wbh);
    cudaGetSymbolAddress(&p_wbl, g_wbl);
    cudaGetSymbolAddress(&p_colcnt, g_colcnt);
    const __nv_bfloat16* wbh = (const __nv_bfloat16*)p_wbh;
    const __nv_bfloat16* wbl = (const __nv_bfloat16*)p_wbl;
    double* stats = (double*)p_stats;   // [4][2*D]

    cudaFuncSetAttribute(k_gemm_mma, cudaFuncAttributeMaxDynamicSharedMemorySize,
                         DYNSMEM);

    // secondary stream + fork/join events (created once; graph-capturable)
    static cudaStream_t s2 = nullptr;
    static cudaEvent_t evA = nullptr, evB = nullptr;
    if (!s2) {
        cudaStreamCreate(&s2);
        cudaEventCreateWithFlags(&evA, cudaEventDisableTiming);
        cudaEventCreateWithFlags(&evB, cudaEventDisableTiming);
    }

    // ---- fork: CSR/degree build + stats zero on s2; wconv+gemm1 main ----
    cudaEventRecord(evA, 0);
    cudaStreamWaitEvent(s2, evA, 0);

    cudaMemsetAsync(p_stats, 0, 4 * 2 * D * sizeof(double), s2);
    cudaMemsetAsync(p_dinv, 0, (size_t)M * sizeof(float), s2);
    cudaMemsetAsync(p_colcnt, 0, (size_t)M * sizeof(int), s2);
    k_count<<<2048, 256, 0, s2>>>(ei, E);
    k_dinv<<<(M + 255) / 256, 256, 0, s2>>>(M);
    const int nb = (M + 1023) / 1024;
    k_scan1<<<nb, 1024, 0, s2>>>(M);
    k_scan2<<<1, 128, 0, s2>>>(nb);
    k_scan3<<<(M + 255) / 256, 256, 0, s2>>>(M, E);
    k_fill<<<2048, 256, 0, s2>>>(ei, ea, E);
    cudaEventRecord(evB, s2);

    const int gemm_grid = (M + BM - 1) / BM;
    k_wconv<<<(4 * WTILE + 255) / 256, 256>>>(Wp[0], Wp[1], Wp[2], Wl);
    // layer-1 GEMM (no BN) overlaps the CSR build
    k_gemm_mma<<<gemm_grid, 256, DYNSMEM>>>(x, wbh, wbl, bp[0],
                                            nullptr, nullptr, nullptr,
                                            (float*)p_h, M);
    cudaStreamWaitEvent(0, evB, 0);   // join before first aggregation

    for (int L = 0; L < 3; L++) {
        if (L > 0)
            k_gemm_mma<<<gemm_grid, 256, DYNSMEM>>>((const float*)p_acc,
                                                    wbh + L * WTILE,
                                                    wbl + L * WTILE, bp[L],
                                                    gp[L - 1], btp[L - 1],
                                                    stats + (L - 1) * 2 * D,
                                                    (float*)p_h, M);
        k_aggr<<<2960, 256>>>((const float*)p_h, Wep[L], bep[L],
                              stats + L * 2 * D, M);
    }
    k_gemm_mma<<<gemm_grid, 256, DYNSMEM>>>((const float*)p_acc,
                                            wbh + 3 * WTILE, wbl + 3 * WTILE,
                                            bl, gp[2], btp[2],
                                            stats + 2 * 2 * D,
                                            (float*)d_out, M);
}

// round 17
// speedup vs baseline: 1.1398x; 1.1398x over previous
#include <cuda_runtime.h>
#include <cuda_bf16.h>
#include <cuda_fp16.h>
#include <cstdint>

#define D 128
#define NMAX 100000
#define EMAX 1600000
#define NBLK 98                         // ceil(NMAX/1024)
#define WTILE (128 * 128)
#define PITCH 272                       // smem row pitch in bytes (136 bf16)
#define BM 64                           // GEMM row-tile (2 CTAs/SM)
#define ATILE64 (BM * PITCH)            // 17408 B (A hi or lo tile)
#define BTILE (128 * PITCH)             // 34816 B (B hi or lo tile)
#define DYNSMEM (2 * ATILE64 + 2 * BTILE)   // 104448 B
#define BN_EPS 1e-5f

// ---- scratch (static device globals; no allocation allowed) ----
__device__ __half  g_h[(size_t)NMAX * D];    // GEMM out (fp16!) / gather src
__device__ float   g_acc[(size_t)NMAX * D];  // aggregation output (fp32)
__device__ float   g_dinv[NMAX];             // deg^-0.5
__device__ double  g_stats4[4][2 * D];       // per-layer BN sum/sumsq
__device__ __align__(16) __nv_bfloat16 g_wbh[4 * WTILE];  // W^T hi (bf16)
__device__ __align__(16) __nv_bfloat16 g_wbl[4 * WTILE];  // W^T lo residual
// CSR-by-destination structures
__device__ int    g_colcnt[NMAX];
__device__ int    g_colptr[NMAX + 1];
__device__ int    g_cursor[NMAX];
__device__ int    g_blksum[NBLK + 1];
__device__ int    g_blkoff[NBLK + 1];
__device__ __align__(16) int4 g_epack[EMAX]; // {row, bits(a0), bits(a1), bits(a2)}
__device__ float  g_enrm[EMAX];              // dinv[row]*dinv[col], edge order

__device__ __forceinline__ uint32_t pack_bf2(__nv_bfloat16 lo, __nv_bfloat16 hi) {
    return ((uint32_t)__bfloat16_as_ushort(hi) << 16) |
           (uint32_t)__bfloat16_as_ushort(lo);
}

// ------------------------------------------------------------------
// Degree (by row, float -> dinv) + in-degree histogram (by col, int)
// ------------------------------------------------------------------
__global__ void k_count(const int* __restrict__ ei, int E) {
    for (int i = blockIdx.x * blockDim.x + threadIdx.x; i < E;
         i += gridDim.x * blockDim.x) {
        atomicAdd(&g_dinv[ei[i]], 1.0f);
        atomicAdd(&g_colcnt[ei[E + i]], 1);
    }
}

__global__ void k_dinv(int M) {
    int i = blockIdx.x * blockDim.x + threadIdx.x;
    if (i < M) g_dinv[i] = rsqrtf(g_dinv[i] + 1.0f);
}

// ---- 3-phase exclusive scan of colcnt -> colptr ----
__global__ void k_scan1(int M) {        // grid=NBLK, block=1024
    __shared__ int sm[1024];
    int tid = threadIdx.x;
    int i   = blockIdx.x * 1024 + tid;
    int v   = (i < M) ? g_colcnt[i] : 0;
    sm[tid] = v;
    __syncthreads();
    #pragma unroll
    for (int off = 1; off < 1024; off <<= 1) {
        int t = (tid >= off) ? sm[tid - off] : 0;
        __syncthreads();
        sm[tid] += t;
        __syncthreads();
    }
    if (i < M) g_colptr[i] = sm[tid] - v;   // block-local exclusive
    if (tid == 1023) g_blksum[blockIdx.x] = sm[1023];
}

__global__ void k_scan2(int nb) {       // 1 block x 128 threads
    __shared__ int sm[128];
    int tid = threadIdx.x;
    int v = (tid < nb) ? g_blksum[tid] : 0;
    sm[tid] = v;
    __syncthreads();
    #pragma unroll
    for (int off = 1; off < 128; off <<= 1) {
        int t = (tid >= off) ? sm[tid - off] : 0;
        __syncthreads();
        sm[tid] += t;
        __syncthreads();
    }
    if (tid <= nb) g_blkoff[tid] = sm[tid] - v;   // exclusive
}

__global__ void k_scan3(int M, int E) {
    int i = blockIdx.x * blockDim.x + threadIdx.x;
    if (i < M) {
        int p = g_colptr[i] + g_blkoff[i >> 10];
        g_colptr[i] = p;
        g_cursor[i] = p;
    }
    if (i == 0) g_colptr[M] = E;
}

// ---- fill packed CSR records + precomputed per-edge norm ----
__global__ void k_fill(const int* __restrict__ ei,
                       const float* __restrict__ ea, int E) {
    for (int i = blockIdx.x * blockDim.x + threadIdx.x; i < E;
         i += gridDim.x * blockDim.x) {
        int r = ei[i], c = ei[E + i];
        int pos = atomicAdd(&g_cursor[c], 1);
        int4 p;
        p.x = r;
        p.y = __float_as_int(ea[3 * i + 0]);
        p.z = __float_as_int(ea[3 * i + 1]);
        p.w = __float_as_int(ea[3 * i + 2]);
        g_epack[pos] = p;
        g_enrm[pos]  = g_dinv[r] * g_dinv[c];
    }
}

// ------------------------------------------------------------------
// Weight conversion: Wt[n][k] = split_bf16(W[k][n]) for 4 matrices
// ------------------------------------------------------------------
__global__ void k_wconv(const float* __restrict__ W0, const float* __restrict__ W1,
                        const float* __restrict__ W2, const float* __restrict__ W3) {
    int i = blockIdx.x * blockDim.x + threadIdx.x;
    if (i >= 4 * WTILE) return;
    int m = i >> 14, r = i & (WTILE - 1);
    int n = r >> 7, k = r & 127;
    const float* W = (m == 0) ? W0 : (m == 1) ? W1 : (m == 2) ? W2 : W3;
    float v = W[k * 128 + n];
    __nv_bfloat16 h = __float2bfloat16_rn(v);
    g_wbh[i] = h;
    g_wbl[i] = __float2bfloat16_rn(v - __bfloat162float(h));
}

// ------------------------------------------------------------------
// Tensor-core split-bf16 GEMM, BM=64 tile (2 CTAs/SM):
//   out = act(A)[M,128] @ W[128,128] + bias
//   act(A) = stats ? relu(A)*mul+add : A  (BN coeffs from stats in-CTA)
//   C = (Ah + Al)@Bh + Ah@Bl
// Output: Ch != null -> fp16 store (intermediate h); else fp32 to C.
// ------------------------------------------------------------------
__global__ __launch_bounds__(256, 2)
void k_gemm_mma(const float* __restrict__ A,
                const __nv_bfloat16* __restrict__ Bh,
                const __nv_bfloat16* __restrict__ Bl,
                const float* __restrict__ bias,
                const float* __restrict__ gam,   // nullable -> no BN
                const float* __restrict__ bet,
                const double* __restrict__ stats,
                float* __restrict__ C,           // fp32 out (final layer)
                __half* __restrict__ Ch,         // fp16 out (intermediate)
                int M)
{
    extern __shared__ char dsm[];
    char* pAh = dsm;
    char* pAl = dsm + ATILE64;
    char* pBh = dsm + 2 * ATILE64;
    char* pBl = dsm + 2 * ATILE64 + BTILE;
    __shared__ float s_bias[128], s_mul[128], s_add[128];

    const int tid  = threadIdx.x;
    const int warp = tid >> 5;
    const int lane = tid & 31;
    const int g    = lane >> 2;
    const int tig  = lane & 3;
    const int m0   = blockIdx.x * BM;
    const bool useBN = (gam != nullptr);

    if (tid < 128) {
        s_bias[tid] = bias[tid];
        if (useBN) {
            double mean = stats[tid] / (double)M;
            double var  = stats[D + tid] / (double)M - mean * mean;
            float mul = gam[tid] * rsqrtf((float)var + BN_EPS);
            s_mul[tid] = mul;
            s_add[tid] = bet[tid] - (float)mean * mul;
        }
    }
    __syncthreads();   // s_mul/s_add read by all threads below

    // B tiles: 128 rows x 128 bf16
    #pragma unroll
    for (int it = 0; it < 8; it++) {
        int q = it * 256 + tid;
        int row = q >> 4, c8 = (q & 15) << 3;
        *(uint4*)(pBh + row * PITCH + c8 * 2) = *(const uint4*)(Bh + row * 128 + c8);
        *(uint4*)(pBl + row * PITCH + c8 * 2) = *(const uint4*)(Bl + row * 128 + c8);
    }

    // A tile: 64 rows, fused relu+BN, split to bf16 hi/lo
    #pragma unroll
    for (int it = 0; it < 8; it++) {
        int q = it * 256 + tid;
        int row = q >> 5, c4 = (q & 31) << 2;
        int grow = m0 + row;
        float4 v = make_float4(0.f, 0.f, 0.f, 0.f);
        if (grow < M) v = *(const float4*)(A + (size_t)grow * 128 + c4);
        float vv[4] = {v.x, v.y, v.z, v.w};
        if (useBN) {
            #pragma unroll
            for (int j = 0; j < 4; j++)
                vv[j] = fmaxf(vv[j], 0.f) * s_mul[c4 + j] + s_add[c4 + j];
        }
        __nv_bfloat16 h[4], l[4];
        #pragma unroll
        for (int j = 0; j < 4; j++) {
            h[j] = __float2bfloat16_rn(vv[j]);
            l[j] = __float2bfloat16_rn(vv[j] - __bfloat162float(h[j]));
        }
        uint2 hw, lw;
        hw.x = pack_bf2(h[0], h[1]); hw.y = pack_bf2(h[2], h[3]);
        lw.x = pack_bf2(l[0], l[1]); lw.y = pack_bf2(l[2], l[3]);
        *(uint2*)(pAh + row * PITCH + c4 * 2) = hw;
        *(uint2*)(pAl + row * PITCH + c4 * 2) = lw;
    }
    __syncthreads();

    float acc[8][4];
    #pragma unroll
    for (int nt = 0; nt < 8; nt++)
        #pragma unroll
        for (int j = 0; j < 4; j++) acc[nt][j] = 0.0f;

    const int arow  = (warp & 3) * 16;
    const int nbase = (warp >> 2) * 64;

    // ---- pass 1: (Ah + Al) @ Bh ----
    #pragma unroll
    for (int k8 = 0; k8 < 8; k8++) {
        uint32_t abase = (uint32_t)(arow + g) * PITCH + (uint32_t)k8 * 32 + 4u * tig;
        uint32_t ah[4], al[4];
        ah[0] = *(const uint32_t*)(pAh + abase);
        ah[1] = *(const uint32_t*)(pAh + abase + 8 * PITCH);
        ah[2] = *(const uint32_t*)(pAh + abase + 16);
        ah[3] = *(const uint32_t*)(pAh + abase + 8 * PITCH + 16);
        al[0] = *(const uint32_t*)(pAl + abase);
        al[1] = *(const uint32_t*)(pAl + abase + 8 * PITCH);
        al[2] = *(const uint32_t*)(pAl + abase + 16);
        al[3] = *(const uint32_t*)(pAl + abase + 8 * PITCH + 16);
        #pragma unroll
        for (int nt = 0; nt < 8; nt++) {
            uint32_t boff = (uint32_t)(nbase + nt * 8 + g) * PITCH + 4u * tig + k8 * 32;
            uint32_t b0 = *(const uint32_t*)(pBh + boff);
            uint32_t b1 = *(const uint32_t*)(pBh + boff + 16);
            asm volatile(
                "mma.sync.aligned.m16n8k16.row.col.f32.bf16.bf16.f32 "
                "{%0,%1,%2,%3}, {%4,%5,%6,%7}, {%8,%9}, {%0,%1,%2,%3};"
                : "+f"(acc[nt][0]), "+f"(acc[nt][1]),
                  "+f"(acc[nt][2]), "+f"(acc[nt][3])
                : "r"(ah[0]), "r"(ah[1]), "r"(ah[2]), "r"(ah[3]),
                  "r"(b0), "r"(b1));
            asm volatile(
                "mma.sync.aligned.m16n8k16.row.col.f32.bf16.bf16.f32 "
                "{%0,%1,%2,%3}, {%4,%5,%6,%7}, {%8,%9}, {%0,%1,%2,%3};"
                : "+f"(acc[nt][0]), "+f"(acc[nt][1]),
                  "+f"(acc[nt][2]), "+f"(acc[nt][3])
                : "r"(al[0]), "r"(al[1]), "r"(al[2]), "r"(al[3]),
                  "r"(b0), "r"(b1));
        }
    }
    // ---- pass 2: Ah @ Bl ----
    #pragma unroll
    for (int k8 = 0; k8 < 8; k8++) {
        uint32_t abase = (uint32_t)(arow + g) * PITCH + (uint32_t)k8 * 32 + 4u * tig;
        uint32_t ah[4];
        ah[0] = *(const uint32_t*)(pAh + abase);
        ah[1] = *(const uint32_t*)(pAh + abase + 8 * PITCH);
        ah[2] = *(const uint32_t*)(pAh + abase + 16);
        ah[3] = *(const uint32_t*)(pAh + abase + 8 * PITCH + 16);
        #pragma unroll
        for (int nt = 0; nt < 8; nt++) {
            uint32_t boff = (uint32_t)(nbase + nt * 8 + g) * PITCH + 4u * tig + k8 * 32;
            uint32_t b0 = *(const uint32_t*)(pBl + boff);
            uint32_t b1 = *(const uint32_t*)(pBl + boff + 16);
            asm volatile(
                "mma.sync.aligned.m16n8k16.row.col.f32.bf16.bf16.f32 "
                "{%0,%1,%2,%3}, {%4,%5,%6,%7}, {%8,%9}, {%0,%1,%2,%3};"
                : "+f"(acc[nt][0]), "+f"(acc[nt][1]),
                  "+f"(acc[nt][2]), "+f"(acc[nt][3])
                : "r"(ah[0]), "r"(ah[1]), "r"(ah[2]), "r"(ah[3]),
                  "r"(b0), "r"(b1));
        }
    }

    const int r0 = m0 + arow + g;
    const int r1 = r0 + 8;
    #pragma unroll
    for (int nt = 0; nt < 8; nt++) {
        int col = nbase + nt * 8 + tig * 2;
        float bx = s_bias[col], by = s_bias[col + 1];
        float v00 = acc[nt][0] + bx, v01 = acc[nt][1] + by;
        float v10 = acc[nt][2] + bx, v11 = acc[nt][3] + by;
        if (Ch) {
            if (r0 < M)
                *(__half2*)(Ch + (size_t)r0 * 128 + col) =
                    __floats2half2_rn(v00, v01);
            if (r1 < M)
                *(__half2*)(Ch + (size_t)r1 * 128 + col) =
                    __floats2half2_rn(v10, v11);
        } else {
            if (r0 < M)
                *(float2*)(C + (size_t)r0 * 128 + col) = make_float2(v00, v01);
            if (r1 < M)
                *(float2*)(C + (size_t)r1 * 128 + col) = make_float2(v10, v11);
        }
    }
}

// ------------------------------------------------------------------
// CSR aggregation + fused BN statistics (R13/R15-proven shape).
// ONE warp per node, lane owns 4 features, masked 8-wide batches.
// h is fp16: per-edge row gather = 256B (2 wavefronts, was 4);
// lane load = 8B uint2 (4 halves), converted to fp32 for the math.
// ------------------------------------------------------------------
__global__ __launch_bounds__(256)
void k_aggr(const __half* __restrict__ h, const float* __restrict__ We,
            const float* __restrict__ be, double* __restrict__ stats, int M)
{
    __shared__ double sm_s[128], sm_s2[128];
    const int tid  = threadIdx.x;
    const int lane = tid & 31;
    const int warp = (blockIdx.x * blockDim.x + tid) >> 5;
    const int nw   = (gridDim.x * blockDim.x) >> 5;
    const int f    = lane << 2;

    if (tid < 128) { sm_s[tid] = 0.0; sm_s2[tid] = 0.0; }
    __syncthreads();

    const float4 w0 = *(const float4*)(We + f);
    const float4 w1 = *(const float4*)(We + D + f);
    const float4 w2 = *(const float4*)(We + 2 * D + f);
    const float4 b4 = *(const float4*)(be + f);

    float ps[4]  = {0.f, 0.f, 0.f, 0.f};
    float ps2[4] = {0.f, 0.f, 0.f, 0.f};

    for (int n = warp; n < M; n += nw) {
        const int beg = g_colptr[n];
        const int end = g_colptr[n + 1];
        float4 acc = make_float4(0.f, 0.f, 0.f, 0.f);

        for (int pos = beg; pos < end; pos += 8) {
            int idx[8];
            #pragma unroll
            for (int u = 0; u < 8; u++) {
                int q = pos + u;
                idx[u] = (q < end) ? q : (end - 1);
            }
            int4  ee[8];
            float nr[8];
            uint2 hr[8];
            #pragma unroll
            for (int u = 0; u < 8; u++) ee[u] = g_epack[idx[u]];
            #pragma unroll
            for (int u = 0; u < 8; u++)
                nr[u] = (pos + u < end) ? g_enrm[idx[u]] : 0.0f;
            #pragma unroll
            for (int u = 0; u < 8; u++)
                hr[u] = *(const uint2*)(h + (size_t)ee[u].x * D + f);
            #pragma unroll
            for (int u = 0; u < 8; u++) {
                float a0 = __int_as_float(ee[u].y);
                float a1 = __int_as_float(ee[u].z);
                float a2 = __int_as_float(ee[u].w);
                float2 h01 = __half22float2(*(__half2*)&hr[u].x);
                float2 h23 = __half22float2(*(__half2*)&hr[u].y);
                acc.x += fmaxf(h01.x + b4.x + a0*w0.x + a1*w1.x + a2*w2.x, 0.f) * nr[u];
                acc.y += fmaxf(h01.y + b4.y + a0*w0.y + a1*w1.y + a2*w2.y, 0.f) * nr[u];
                acc.z += fmaxf(h23.x + b4.z + a0*w0.z + a1*w1.z + a2*w2.z, 0.f) * nr[u];
                acc.w += fmaxf(h23.y + b4.w + a0*w0.w + a1*w1.w + a2*w2.w, 0.f) * nr[u];
            }
        }
        *(float4*)(g_acc + (size_t)n * D + f) = acc;

        // fused BN stats over relu(acc)
        float r0 = fmaxf(acc.x, 0.f), r1 = fmaxf(acc.y, 0.f);
        float r2 = fmaxf(acc.z, 0.f), r3 = fmaxf(acc.w, 0.f);
        ps[0] += r0; ps2[0] += r0 * r0;
        ps[1] += r1; ps2[1] += r1 * r1;
        ps[2] += r2; ps2[2] += r2 * r2;
        ps[3] += r3; ps2[3] += r3 * r3;
    }

    #pragma unroll
    for (int j = 0; j < 4; j++) {
        atomicAdd(&sm_s[f + j],  (double)ps[j]);
        atomicAdd(&sm_s2[f + j], (double)ps2[j]);
    }
    __syncthreads();
    if (tid < 128) {
        atomicAdd(&stats[tid],     sm_s[tid]);
        atomicAdd(&stats[D + tid], sm_s2[tid]);
    }
}

// ------------------------------------------------------------------
extern "C" void kernel_launch(void* const* d_in, const int* in_sizes, int n_in,
                              void* d_out, int out_size)
{
    const float* x  = (const float*)d_in[0];
    const int*   ei = (const int*)d_in[1];
    const float* ea = (const float*)d_in[2];
    const float* Wp[3]  = {(const float*)d_in[3],  (const float*)d_in[9],  (const float*)d_in[15]};
    const float* bp[3]  = {(const float*)d_in[4],  (const float*)d_in[10], (const float*)d_in[16]};
    const float* Wep[3] = {(const float*)d_in[5],  (const float*)d_in[11], (const float*)d_in[17]};
    const float* bep[3] = {(const float*)d_in[6],  (const float*)d_in[12], (const float*)d_in[18]};
    const float* gp[3]  = {(const float*)d_in[7],  (const float*)d_in[13], (const float*)d_in[19]};
    const float* btp[3] = {(const float*)d_in[8],  (const float*)d_in[14], (const float*)d_in[20]};
    const float* Wl = (const float*)d_in[21];
    const float* bl = (const float*)d_in[22];

    const int M = in_sizes[0] / D;
    const int E = in_sizes[1] / 2;

    // Resolve __device__ symbols via the runtime (GB300 ATS pitfall).
    void *p_h, *p_acc, *p_dinv, *p_stats, *p_wbh, *p_wbl, *p_colcnt;
    cudaGetSymbolAddress(&p_h, g_h);
    cudaGetSymbolAddress(&p_acc, g_acc);
    cudaGetSymbolAddress(&p_dinv, g_dinv);
    cudaGetSymbolAddress(&p_stats, g_stats4);
    cudaGetSymbolAddress(&p_wbh, g_wbh);
    cudaGetSymbolAddress(&p_wbl, g_wbl);
    cudaGetSymbolAddress(&p_colcnt, g_colcnt);
    const __nv_bfloat16* wbh = (const __nv_bfloat16*)p_wbh;
    const __nv_bfloat16* wbl = (const __nv_bfloat16*)p_wbl;
    double* stats = (double*)p_stats;   // [4][2*D]
    __half* hbuf  = (__half*)p_h;

    cudaFuncSetAttribute(k_gemm_mma, cudaFuncAttributeMaxDynamicSharedMemorySize,
                         DYNSMEM);

    // secondary stream + fork/join events (created once; graph-capturable)
    static cudaStream_t s2 = nullptr;
    static cudaEvent_t evA = nullptr, evB = nullptr;
    if (!s2) {
        cudaStreamCreate(&s2);
        cudaEventCreateWithFlags(&evA, cudaEventDisableTiming);
        cudaEventCreateWithFlags(&evB, cudaEventDisableTiming);
    }

    // ---- fork: CSR/degree build + stats zero on s2; wconv+gemm1 main ----
    cudaEventRecord(evA, 0);
    cudaStreamWaitEvent(s2, evA, 0);

    cudaMemsetAsync(p_stats, 0, 4 * 2 * D * sizeof(double), s2);
    cudaMemsetAsync(p_dinv, 0, (size_t)M * sizeof(float), s2);
    cudaMemsetAsync(p_colcnt, 0, (size_t)M * sizeof(int), s2);
    k_count<<<2048, 256, 0, s2>>>(ei, E);
    k_dinv<<<(M + 255) / 256, 256, 0, s2>>>(M);
    const int nb = (M + 1023) / 1024;
    k_scan1<<<nb, 1024, 0, s2>>>(M);
    k_scan2<<<1, 128, 0, s2>>>(nb);
    k_scan3<<<(M + 255) / 256, 256, 0, s2>>>(M, E);
    k_fill<<<2048, 256, 0, s2>>>(ei, ea, E);
    cudaEventRecord(evB, s2);

    const int gemm_grid = (M + BM - 1) / BM;
    k_wconv<<<(4 * WTILE + 255) / 256, 256>>>(Wp[0], Wp[1], Wp[2], Wl);
    // layer-1 GEMM (no BN) overlaps the CSR build; fp16 output
    k_gemm_mma<<<gemm_grid, 256, DYNSMEM>>>(x, wbh, wbl, bp[0],
                                            nullptr, nullptr, nullptr,
                                            nullptr, hbuf, M);
    cudaStreamWaitEvent(0, evB, 0);   // join before first aggregation

    for (int L = 0; L < 3; L++) {
        if (L > 0)
            k_gemm_mma<<<gemm_grid, 256, DYNSMEM>>>((const float*)p_acc,
                                                    wbh + L * WTILE,
                                                    wbl + L * WTILE, bp[L],
                                                    gp[L - 1], btp[L - 1],
                                                    stats + (L - 1) * 2 * D,
                                                    nullptr, hbuf, M);
        k_aggr<<<2048, 256>>>((const __half*)p_h, Wep[L], bep[L],
                              stats + L * 2 * D, M);
    }
    // final GEMM: fp32 output to d_out
    k_gemm_mma<<<gemm_grid, 256, DYNSMEM>>>((const float*)p_acc,
                                            wbh + 3 * WTILE, wbl + 3 * WTILE,
                                            bl, gp[2], btp[2],
                                            stats + 2 * 2 * D,
                                            (float*)d_out, nullptr, M);
}